// round 1
// baseline (speedup 1.0000x reference)
#include <cuda_runtime.h>
#include <math.h>

#define BB 8
#define LL 1000
#define DD 512
#define HH 8
#define DKK 64
#define NTOK (BB*LL)
#define RELN (2*LL-1)

// scratch (device globals: no allocations allowed)
__device__ float g_xn[NTOK*DD];
__device__ float g_q[NTOK*DD];   // layout (B,H,L,dk)
__device__ float g_k[NTOK*DD];
__device__ float g_v[NTOK*DD];
__device__ float g_ctx[NTOK*DD]; // layout (B,L,D)

// ---------------------------------------------------------------- LayerNorm
__global__ __launch_bounds__(128) void ln_kernel(const float* __restrict__ x,
                                                 const float* __restrict__ gamma,
                                                 const float* __restrict__ beta)
{
    int tok = blockIdx.x;
    int tid = threadIdx.x;
    const float4 v = reinterpret_cast<const float4*>(x + (size_t)tok * DD)[tid];
    float s  = v.x + v.y + v.z + v.w;
    float ss = v.x*v.x + v.y*v.y + v.z*v.z + v.w*v.w;
#pragma unroll
    for (int o = 16; o; o >>= 1) {
        s  += __shfl_xor_sync(0xffffffffu, s,  o);
        ss += __shfl_xor_sync(0xffffffffu, ss, o);
    }
    __shared__ float sh[8];
    int w = tid >> 5, lane = tid & 31;
    if (lane == 0) { sh[w] = s; sh[4 + w] = ss; }
    __syncthreads();
    s  = sh[0] + sh[1] + sh[2] + sh[3];
    ss = sh[4] + sh[5] + sh[6] + sh[7];
    float mu  = s * (1.0f / DD);
    float var = ss * (1.0f / DD) - mu * mu;
    float inv = rsqrtf(var + 1e-5f);
    float4 g = reinterpret_cast<const float4*>(gamma)[tid];
    float4 b = reinterpret_cast<const float4*>(beta)[tid];
    float4 o4;
    o4.x = (v.x - mu) * inv * g.x + b.x;
    o4.y = (v.y - mu) * inv * g.y + b.y;
    o4.z = (v.z - mu) * inv * g.z + b.z;
    o4.w = (v.w - mu) * inv * g.w + b.w;
    reinterpret_cast<float4*>(g_xn + (size_t)tok * DD)[tid] = o4;
}

// ------------------------------------------------- tiled SGEMM  C = A @ W^T + bias
// mode 0: scatter to (B,H,L,dk) layout (QKV projections)
// mode 1: row-major out + residual (output projection)
__global__ __launch_bounds__(256) void gemm_kernel(const float* __restrict__ A,
                                                   const float* __restrict__ W,
                                                   const float* __restrict__ bias,
                                                   float* __restrict__ Cout,
                                                   const float* __restrict__ res,
                                                   int mode)
{
    __shared__ float As[16][68];
    __shared__ float Bs[16][68];
    int tid = threadIdx.x;
    int tx = tid & 15, ty = tid >> 4;
    int m0 = blockIdx.y << 6;
    int n0 = blockIdx.x << 6;
    float acc[4][4] = {};

    for (int k0 = 0; k0 < DD; k0 += 16) {
#pragma unroll
        for (int i = 0; i < 4; i++) {
            int idx = tid + (i << 8);
            int r = idx >> 4, kk = idx & 15;
            As[kk][r] = A[(size_t)(m0 + r) * DD + k0 + kk];
            Bs[kk][r] = W[(size_t)(n0 + r) * DD + k0 + kk];
        }
        __syncthreads();
#pragma unroll
        for (int kk = 0; kk < 16; kk++) {
            float4 a4 = *reinterpret_cast<const float4*>(&As[kk][ty << 2]);
            float4 b4 = *reinterpret_cast<const float4*>(&Bs[kk][tx << 2]);
            float av[4] = {a4.x, a4.y, a4.z, a4.w};
            float bv[4] = {b4.x, b4.y, b4.z, b4.w};
#pragma unroll
            for (int i = 0; i < 4; i++)
#pragma unroll
                for (int j = 0; j < 4; j++)
                    acc[i][j] += av[i] * bv[j];
        }
        __syncthreads();
    }

    float4 bb4 = *reinterpret_cast<const float4*>(&bias[n0 + (tx << 2)]);
    float bv[4] = {bb4.x, bb4.y, bb4.z, bb4.w};
#pragma unroll
    for (int i = 0; i < 4; i++) {
        int mg = m0 + (ty << 2) + i;
        if (mode == 0) {
            int bidx = mg / LL, l = mg - bidx * LL;
            int o0 = n0 + (tx << 2);       // h = o0>>6 constant within the quad
            int h = o0 >> 6, dd = o0 & 63;
            float4 o4 = make_float4(acc[i][0] + bv[0], acc[i][1] + bv[1],
                                    acc[i][2] + bv[2], acc[i][3] + bv[3]);
            *reinterpret_cast<float4*>(
                &Cout[(size_t)bidx * (LL * DD) + (size_t)h * (LL * DKK) +
                      (size_t)l * DKK + dd]) = o4;
        } else {
            size_t off = (size_t)mg * DD + n0 + (tx << 2);
            float4 r4 = *reinterpret_cast<const float4*>(&res[off]);
            float4 o4 = make_float4(acc[i][0] + bv[0] + r4.x, acc[i][1] + bv[1] + r4.y,
                                    acc[i][2] + bv[2] + r4.z, acc[i][3] + bv[3] + r4.w);
            *reinterpret_cast<float4*>(&Cout[off]) = o4;
        }
    }
}

// --------------------------------------------------------- flash attention
// per block: 64 query rows of one (b,h); loop over 16 key tiles of 64.
// S = scale * Q@K^T + gather(R),  R = Q @ Rel_band^T (127-wide Toeplitz band)
#define ATTN_SMEM_FLOATS (3*64*68 + 64*132)

__global__ __launch_bounds__(256, 2) void attn_kernel(const float* __restrict__ rel)
{
    extern __shared__ float smf[];
    float* sQt  = smf;              // [64 d][68]  Q^T
    float* sKP  = smf + 64*68;      // [64 d][68]  K^T, later P^T [64 jj][68]
    float* sV   = smf + 2*64*68;    // [64 jj][68] V
    float* sRel = smf + 3*64*68;    // [64 d][132] Rel^T, later R [64 r][132]

    const int tid = threadIdx.x;
    const int tx = tid & 15, ty = tid >> 4;
    const int bh = blockIdx.y;
    const int i0 = blockIdx.x << 6;
    const float* qb = g_q + (size_t)bh * LL * DKK;
    const float* kb = g_k + (size_t)bh * LL * DKK;
    const float* vb = g_v + (size_t)bh * LL * DKK;

    // load Q tile transposed (zero-fill rows >= L)
#pragma unroll
    for (int it = 0; it < 4; it++) {
        int f = tid + (it << 8);
        int r = f >> 4;
        int d4 = (f & 15) << 2;
        int rg = i0 + r;
        float4 qv = make_float4(0.f, 0.f, 0.f, 0.f);
        if (rg < LL) qv = *reinterpret_cast<const float4*>(qb + (size_t)rg * DKK + d4);
        sQt[(d4 + 0) * 68 + r] = qv.x;
        sQt[(d4 + 1) * 68 + r] = qv.y;
        sQt[(d4 + 2) * 68 + r] = qv.z;
        sQt[(d4 + 3) * 68 + r] = qv.w;
    }

    float oacc[4][4] = {};
    float mrow[4] = {-1e30f, -1e30f, -1e30f, -1e30f};
    float lrow[4] = {};
    const float scale = 0.125f;  // 1/sqrt(64)

    for (int j0 = 0; j0 < LL; j0 += 64) {
        __syncthreads();  // protect sKP/sV/sRel from previous iteration readers
        // K^T and V tiles
#pragma unroll
        for (int it = 0; it < 4; it++) {
            int f = tid + (it << 8);
            int r = f >> 4;
            int d4 = (f & 15) << 2;
            int jg = j0 + r;
            float4 kv = make_float4(0.f, 0.f, 0.f, 0.f);
            float4 vv = make_float4(0.f, 0.f, 0.f, 0.f);
            if (jg < LL) {
                kv = *reinterpret_cast<const float4*>(kb + (size_t)jg * DKK + d4);
                vv = *reinterpret_cast<const float4*>(vb + (size_t)jg * DKK + d4);
            }
            sKP[(d4 + 0) * 68 + r] = kv.x;
            sKP[(d4 + 1) * 68 + r] = kv.y;
            sKP[(d4 + 2) * 68 + r] = kv.z;
            sKP[(d4 + 3) * 68 + r] = kv.w;
            *reinterpret_cast<float4*>(&sV[r * 68 + d4]) = vv;
        }
        // rel band: 128 rows starting at mbase (zero-fill out of range)
        int mbase = j0 - i0 + (LL - 1) - 63;
#pragma unroll
        for (int it = 0; it < 8; it++) {
            int f = tid + (it << 8);
            int r = f >> 4;            // 0..127
            int d4 = (f & 15) << 2;
            int mg = mbase + r;
            float4 rv = make_float4(0.f, 0.f, 0.f, 0.f);
            if (mg >= 0 && mg < RELN)
                rv = *reinterpret_cast<const float4*>(rel + (size_t)mg * DKK + d4);
            sRel[(d4 + 0) * 132 + r] = rv.x;
            sRel[(d4 + 1) * 132 + r] = rv.y;
            sRel[(d4 + 2) * 132 + r] = rv.z;
            sRel[(d4 + 3) * 132 + r] = rv.w;
        }
        __syncthreads();

        // fused GEMMs: S_qk (64x64) and R band (64x128), shared A-fragment
        float sqk[4][4] = {};
        float rr[4][8] = {};
#pragma unroll 8
        for (int d = 0; d < 64; d++) {
            float4 a4 = *reinterpret_cast<const float4*>(&sQt[d * 68 + (ty << 2)]);
            float4 k4 = *reinterpret_cast<const float4*>(&sKP[d * 68 + (tx << 2)]);
            float4 r0 = *reinterpret_cast<const float4*>(&sRel[d * 132 + (tx << 3)]);
            float4 r1 = *reinterpret_cast<const float4*>(&sRel[d * 132 + (tx << 3) + 4]);
            float av[4] = {a4.x, a4.y, a4.z, a4.w};
            float kv[4] = {k4.x, k4.y, k4.z, k4.w};
            float rv[8] = {r0.x, r0.y, r0.z, r0.w, r1.x, r1.y, r1.z, r1.w};
#pragma unroll
            for (int i = 0; i < 4; i++) {
#pragma unroll
                for (int j = 0; j < 4; j++) sqk[i][j] += av[i] * kv[j];
#pragma unroll
                for (int j = 0; j < 8; j++) rr[i][j] += av[i] * rv[j];
            }
        }
        __syncthreads();
        // write R over the rel buffer (row-major)
#pragma unroll
        for (int i = 0; i < 4; i++)
#pragma unroll
            for (int j = 0; j < 8; j++)
                sRel[((ty << 2) + i) * 132 + (tx << 3) + j] = rr[i][j];
        __syncthreads();

        // gather + online softmax (rows ty*4+i; 16 lanes of same ty share a row)
        float p[4][4];
#pragma unroll
        for (int i = 0; i < 4; i++) {
            int row = (ty << 2) + i;
            float mx = -1e30f;
#pragma unroll
            for (int j = 0; j < 4; j++) {
                int col = (tx << 2) + j;
                float sc = sqk[i][j] * scale + sRel[row * 132 + (col - row + 63)];
                if (j0 + col >= LL) sc = -1e30f;
                p[i][j] = sc;
                mx = fmaxf(mx, sc);
            }
#pragma unroll
            for (int o = 1; o < 16; o <<= 1)
                mx = fmaxf(mx, __shfl_xor_sync(0xffffffffu, mx, o));
            float mnew = fmaxf(mrow[i], mx);
            float corr = __expf(mrow[i] - mnew);
            mrow[i] = mnew;
            float ls = 0.f;
#pragma unroll
            for (int j = 0; j < 4; j++) {
                p[i][j] = __expf(p[i][j] - mnew);
                ls += p[i][j];
            }
#pragma unroll
            for (int o = 1; o < 16; o <<= 1)
                ls += __shfl_xor_sync(0xffffffffu, ls, o);
            lrow[i] = lrow[i] * corr + ls;
#pragma unroll
            for (int j = 0; j < 4; j++) oacc[i][j] *= corr;
        }
        // P^T into sKP (K tile fully consumed)
#pragma unroll
        for (int i = 0; i < 4; i++)
#pragma unroll
            for (int j = 0; j < 4; j++)
                sKP[((tx << 2) + j) * 68 + (ty << 2) + i] = p[i][j];
        __syncthreads();

        // O += P @ V
#pragma unroll 8
        for (int jj = 0; jj < 64; jj++) {
            float4 pa = *reinterpret_cast<const float4*>(&sKP[jj * 68 + (ty << 2)]);
            float4 v4 = *reinterpret_cast<const float4*>(&sV[jj * 68 + (tx << 2)]);
            float pv[4] = {pa.x, pa.y, pa.z, pa.w};
            float vv[4] = {v4.x, v4.y, v4.z, v4.w};
#pragma unroll
            for (int i = 0; i < 4; i++)
#pragma unroll
                for (int j = 0; j < 4; j++)
                    oacc[i][j] += pv[i] * vv[j];
        }
    }

    // epilogue: normalize and scatter to (B,L,D)
    int b = bh >> 3, h = bh & 7;
#pragma unroll
    for (int i = 0; i < 4; i++) {
        int rg = i0 + (ty << 2) + i;
        if (rg < LL) {
            float invl = 1.0f / lrow[i];
            float4 o4 = make_float4(oacc[i][0] * invl, oacc[i][1] * invl,
                                    oacc[i][2] * invl, oacc[i][3] * invl);
            *reinterpret_cast<float4*>(
                &g_ctx[((size_t)b * LL + rg) * DD + h * 64 + (tx << 2)]) = o4;
        }
    }
}

// ---------------------------------------------------------------- launcher
extern "C" void kernel_launch(void* const* d_in, const int* in_sizes, int n_in,
                              void* d_out, int out_size)
{
    const float* x     = (const float*)d_in[0];
    const float* Wq    = (const float*)d_in[1];
    const float* bq    = (const float*)d_in[2];
    const float* Wk    = (const float*)d_in[3];
    const float* bk    = (const float*)d_in[4];
    const float* Wv    = (const float*)d_in[5];
    const float* bv    = (const float*)d_in[6];
    const float* Wo    = (const float*)d_in[7];
    const float* bo    = (const float*)d_in[8];
    const float* rel   = (const float*)d_in[9];
    const float* gamma = (const float*)d_in[10];
    const float* beta  = (const float*)d_in[11];
    float* out = (float*)d_out;

    float *xn, *q, *k, *v, *ctx;
    cudaGetSymbolAddress((void**)&xn,  g_xn);
    cudaGetSymbolAddress((void**)&q,   g_q);
    cudaGetSymbolAddress((void**)&k,   g_k);
    cudaGetSymbolAddress((void**)&v,   g_v);
    cudaGetSymbolAddress((void**)&ctx, g_ctx);

    cudaFuncSetAttribute(attn_kernel, cudaFuncAttributeMaxDynamicSharedMemorySize,
                         ATTN_SMEM_FLOATS * (int)sizeof(float));

    ln_kernel<<<NTOK, 128>>>(x, gamma, beta);

    dim3 gg(DD / 64, NTOK / 64);  // (8, 125)
    gemm_kernel<<<gg, 256>>>(xn, Wq, bq, q, nullptr, 0);
    gemm_kernel<<<gg, 256>>>(xn, Wk, bk, k, nullptr, 0);
    gemm_kernel<<<gg, 256>>>(xn, Wv, bv, v, nullptr, 0);

    dim3 ga((LL + 63) / 64, BB * HH);  // (16, 64)
    attn_kernel<<<ga, 256, ATTN_SMEM_FLOATS * sizeof(float)>>>(rel);

    gemm_kernel<<<gg, 256>>>(ctx, Wo, bo, out, x, 1);
}